// round 11
// baseline (speedup 1.0000x reference)
#include <cuda_runtime.h>
#include <cuda_bf16.h>
#include <cstdint>

#define SCALING 0.125f

// ---------------------------------------------------------------------------
// helpers
// ---------------------------------------------------------------------------
__device__ __forceinline__ uint32_t s2u(const void* p) {
    uint32_t a;
    asm("{ .reg .u64 t; cvta.to.shared.u64 t, %1; cvt.u32.u64 %0, t; }"
        : "=r"(a) : "l"(p));
    return a;
}
__device__ __forceinline__ uint32_t pk2(float a, float b) {
    __nv_bfloat162 t = __floats2bfloat162_rn(a, b);
    return reinterpret_cast<uint32_t&>(t);
}
__device__ __forceinline__ float bhi(float x) {
    return __bfloat162float(__float2bfloat16(x));
}
__device__ __forceinline__ void ldsm4(uint32_t* r, uint32_t addr) {
    asm volatile("ldmatrix.sync.aligned.m8n8.x4.shared.b16 {%0,%1,%2,%3}, [%4];"
        : "=r"(r[0]), "=r"(r[1]), "=r"(r[2]), "=r"(r[3]) : "r"(addr));
}
__device__ __forceinline__ void mma_bf16(float* c, const uint32_t* a, const uint32_t* b) {
    asm volatile(
        "mma.sync.aligned.m16n8k16.row.col.f32.bf16.bf16.f32 "
        "{%0,%1,%2,%3}, {%4,%5,%6,%7}, {%8,%9}, {%0,%1,%2,%3};"
        : "+f"(c[0]), "+f"(c[1]), "+f"(c[2]), "+f"(c[3])
        : "r"(a[0]), "r"(a[1]), "r"(a[2]), "r"(a[3]), "r"(b[0]), "r"(b[1]));
}
#define SWZ(x) ((x) ^ (((x) >> 3) & 0x70))

#define CP_ASYNC16(dst, src) \
    asm volatile("cp.async.cg.shared.global [%0], [%1], 16;" :: "r"(dst), "l"(src))
#define CP_COMMIT() asm volatile("cp.async.commit_group;")
#define CP_WAIT0()  asm volatile("cp.async.wait_group 0;")
#define CP_WAIT1()  asm volatile("cp.async.wait_group 1;")
#define CP_WAIT2()  asm volatile("cp.async.wait_group 2;")

// ---------------------------------------------------------------------------
// Device scratch
// ---------------------------------------------------------------------------
__device__ __align__(16) __nv_bfloat16 g_qin_h[2048 * 1024], g_qin_l[2048 * 1024];
__device__ __align__(16) __nv_bfloat16 g_kin_h[2048 * 1024], g_kin_l[2048 * 1024];
__device__ __align__(16) __nv_bfloat16 g_wq_h[1024 * 1024], g_wq_l[1024 * 1024];
__device__ __align__(16) __nv_bfloat16 g_wk_h[1024 * 1024], g_wk_l[1024 * 1024];
__device__ __align__(16) __nv_bfloat16 g_wv_h[1024 * 1024], g_wv_l[1024 * 1024];
__device__ __align__(16) __nv_bfloat16 g_wo_h[1024 * 1024], g_wo_l[1024 * 1024];
__device__ __align__(16) __nv_bfloat16 g_qp_h[2048 * 1024], g_qp_l[2048 * 1024];
__device__ __align__(16) __nv_bfloat16 g_kp_h[2048 * 1024], g_kp_l[2048 * 1024];
__device__ __align__(16) float g_vp[2048 * 1024];
__device__ __align__(16) float g_qk[(size_t)32 * 1024 * 1024];
__device__ __align__(16) __nv_bfloat16 g_E_h[(size_t)32 * 1024 * 1024];
__device__ __align__(16) __nv_bfloat16 g_E_l[(size_t)32 * 1024 * 1024];
__device__ __align__(16) float g_rZ[32 * 4 * 1024];
__device__ __align__(16) float g_emg[2 * 4 * 1024];
__device__ __align__(16) __nv_bfloat16 g_vgt_h[32 * 256 * 1024], g_vgt_l[32 * 256 * 1024];
// attO layout: [b][g][t][d]
__device__ __align__(16) __nv_bfloat16 g_aO_h[8192 * 1024], g_aO_l[8192 * 1024];

// ---------------------------------------------------------------------------
// K0: fused fp32 -> bf16 hi/lo split over 5 tensors
// ---------------------------------------------------------------------------
struct SplitArgs {
    const float* src[5];
    __nv_bfloat16* h[5];
    __nv_bfloat16* l[5];
    int end[5];
};

__global__ __launch_bounds__(256) void split_all_kernel(SplitArgs args)
{
    int i = blockIdx.x * 256 + threadIdx.x;
    int reg = 0;
#pragma unroll
    for (int r = 0; r < 4; r++) reg += (i >= args.end[r]) ? 1 : 0;
    int base = (reg == 0) ? 0 : args.end[reg - 1];
    int j = i - base;
    float4 v = ((const float4*)args.src[reg])[j];
    float h0 = bhi(v.x), h1 = bhi(v.y), h2 = bhi(v.z), h3 = bhi(v.w);
    ((uint2*)args.h[reg])[j] = make_uint2(pk2(h0, h1), pk2(h2, h3));
    ((uint2*)args.l[reg])[j] =
        make_uint2(pk2(v.x - h0, v.y - h1), pk2(v.z - h2, v.w - h3));
}

__global__ __launch_bounds__(256) void split_one_kernel(
    const float* __restrict__ x, __nv_bfloat16* __restrict__ h,
    __nv_bfloat16* __restrict__ l)
{
    int i = blockIdx.x * 256 + threadIdx.x;
    float4 v = ((const float4*)x)[i];
    float h0 = bhi(v.x), h1 = bhi(v.y), h2 = bhi(v.z), h3 = bhi(v.w);
    ((uint2*)h)[i] = make_uint2(pk2(h0, h1), pk2(h2, h3));
    ((uint2*)l)[i] = make_uint2(pk2(v.x - h0, v.y - h1), pk2(v.z - h2, v.w - h3));
}

// ---------------------------------------------------------------------------
// prep: emg[b][g][s] = exp(gmask[b,g,s]) masked
// ---------------------------------------------------------------------------
__global__ __launch_bounds__(256) void prep_em(
    const float* __restrict__ gmask, const unsigned char* __restrict__ kpm,
    float* __restrict__ emg)
{
    int i = blockIdx.x * 256 + threadIdx.x;
    int b = i >> 12, s = i & 1023;
    float e = __expf(gmask[i]);
    if (kpm[b * 1024 + s]) e = 0.f;
    emg[i] = e;
}

// ---------------------------------------------------------------------------
// GEMM core: bf16x3 mma.sync, cp.async 3-stage, BK=32
// ---------------------------------------------------------------------------
#define GEMM_SMEM 98304

__device__ __forceinline__ void gemm_core(
    const __nv_bfloat16* __restrict__ Ah, const __nv_bfloat16* __restrict__ Al,
    const __nv_bfloat16* __restrict__ Bh, const __nv_bfloat16* __restrict__ Bl,
    size_t a_base, int a_str, size_t b_base, int b_str,
    int Kchunks, uint32_t sbase, int tid, int wm, int wn,
    float acc[4][4][4])
{
    const int lane = tid & 31;
    const int a_r  = lane & 15;
    const int a_kb = (lane >> 4) * 16;
    const int b_r  = (lane & 7) + ((lane >> 4) & 1) * 8;
    const int b_kb = ((lane >> 3) & 1) * 16;

#define ISSUE(kc, st) do {                                                     \
    const int _k0 = (kc) * 32;                                                 \
    _Pragma("unroll")                                                          \
    for (int it = 0; it < 8; it++) {                                           \
        int j = it * 256 + tid;                                                \
        int buf = j >> 10;                                                     \
        int r = (j >> 3) & 127;                                                \
        int ch = j & 7;                                                        \
        const __nv_bfloat16* src = buf ? (ch < 4 ? Bh : Bl)                    \
                                       : (ch < 4 ? Ah : Al);                   \
        size_t bs = buf ? b_base : a_base;                                     \
        int strd = buf ? b_str : a_str;                                        \
        uint32_t d = sbase + (st) * 32768 + buf * 16384 + SWZ(r * 128 + ch * 16);\
        CP_ASYNC16(d, src + bs + _k0 + (size_t)r * strd + (ch & 3) * 8);       \
    }                                                                          \
    CP_COMMIT();                                                               \
} while (0)

    ISSUE(0, 0);
    if (Kchunks > 1) ISSUE(1, 1);

    for (int kc = 0; kc < Kchunks; kc++) {
        const int st = kc % 3;
        if (kc + 2 < Kchunks) {
            ISSUE(kc + 2, (kc + 2) % 3);
            CP_WAIT2();
        } else if (kc + 1 < Kchunks) {
            CP_WAIT1();
        } else {
            CP_WAIT0();
        }
        __syncthreads();

        const uint32_t sA = sbase + st * 32768;
        const uint32_t sB = sA + 16384;

#pragma unroll
        for (int ks = 0; ks < 2; ks++) {
            const int kbb = ks * 32;
            uint32_t ah[4][4], bb[2][4];
#pragma unroll
            for (int mi = 0; mi < 4; mi++)
                ldsm4(ah[mi], sA + SWZ((wm + 16 * mi + a_r) * 128 + kbb + a_kb));
#pragma unroll
            for (int jj = 0; jj < 2; jj++)
                ldsm4(bb[jj], sB + SWZ((wn + 16 * jj + b_r) * 128 + kbb + b_kb));
#pragma unroll
            for (int mi = 0; mi < 4; mi++)
#pragma unroll
                for (int nj = 0; nj < 4; nj++)
                    mma_bf16(acc[mi][nj], ah[mi], &bb[nj >> 1][(nj & 1) * 2]);
#pragma unroll
            for (int mi = 0; mi < 4; mi++) {
                uint32_t al[4];
                ldsm4(al, sA + SWZ((wm + 16 * mi + a_r) * 128 + 64 + kbb + a_kb));
#pragma unroll
                for (int nj = 0; nj < 4; nj++)
                    mma_bf16(acc[mi][nj], al, &bb[nj >> 1][(nj & 1) * 2]);
            }
#pragma unroll
            for (int jj = 0; jj < 2; jj++)
                ldsm4(bb[jj], sB + SWZ((wn + 16 * jj + b_r) * 128 + 64 + kbb + b_kb));
#pragma unroll
            for (int mi = 0; mi < 4; mi++)
#pragma unroll
                for (int nj = 0; nj < 4; nj++)
                    mma_bf16(acc[mi][nj], ah[mi], &bb[nj >> 1][(nj & 1) * 2]);
        }
        __syncthreads();
    }
#undef ISSUE
}

// ---------------------------------------------------------------------------
// fused Q/K projection GEMM: z = 0:Q, 1:K
// ---------------------------------------------------------------------------
struct QKVArgs {
    const __nv_bfloat16 *qh, *ql, *kh, *kl;
    const __nv_bfloat16 *wqh, *wql, *wkh, *wkl;
    const float *bq, *bk;
    __nv_bfloat16 *qph, *qpl, *kph, *kpl;
};

__global__ __launch_bounds__(256, 2) void gemm_qkproj(QKVArgs a)
{
    extern __shared__ __align__(1024) char smem[];
    const uint32_t sbase = s2u(smem);
    const int tid = threadIdx.x;
    const int wid = tid >> 5, lane = tid & 31;
    const int m0 = blockIdx.y * 128, n0 = blockIdx.x * 128;
    const int z = blockIdx.z;

    const __nv_bfloat16* Ah = (z == 0) ? a.qh : a.kh;
    const __nv_bfloat16* Al = (z == 0) ? a.ql : a.kl;
    const __nv_bfloat16* Bh = (z == 0) ? a.wqh : a.wkh;
    const __nv_bfloat16* Bl = (z == 0) ? a.wql : a.wkl;
    const float* bias = (z == 0) ? a.bq : a.bk;
    const float scale = (z == 0) ? SCALING : 1.0f;
    __nv_bfloat16* Ch = (z == 0) ? a.qph : a.kph;
    __nv_bfloat16* Cl = (z == 0) ? a.qpl : a.kpl;

    const int wm = (wid >> 2) * 64, wn = (wid & 3) * 32;

    float acc[4][4][4];
#pragma unroll
    for (int i = 0; i < 4; i++)
#pragma unroll
        for (int j = 0; j < 4; j++)
#pragma unroll
            for (int e = 0; e < 4; e++) acc[i][j][e] = 0.f;

    gemm_core(Ah, Al, Bh, Bl, (size_t)m0 * 1024, 1024, (size_t)n0 * 1024, 1024,
              32, sbase, tid, wm, wn, acc);

    const int tr = lane >> 2, tc2 = (lane & 3) * 2;
#pragma unroll
    for (int mi = 0; mi < 4; mi++) {
#pragma unroll
        for (int nj = 0; nj < 4; nj++) {
            int n = n0 + wn + 8 * nj + tc2;
#pragma unroll
            for (int hr = 0; hr < 2; hr++) {
                int m = m0 + wm + 16 * mi + tr + hr * 8;
                float v0 = acc[mi][nj][hr * 2 + 0];
                float v1 = acc[mi][nj][hr * 2 + 1];
                float y0 = (v0 + bias[n]) * scale, y1 = (v1 + bias[n + 1]) * scale;
                float h0 = bhi(y0), h1 = bhi(y1);
                size_t o = ((size_t)m * 1024 + n) >> 1;
                ((uint32_t*)Ch)[o] = pk2(h0, h1);
                ((uint32_t*)Cl)[o] = pk2(y0 - h0, y1 - h1);
            }
        }
    }
}

// ---------------------------------------------------------------------------
// generic GEMM: MODE 1 vproj, 2 qk, 3 pv, 4 oproj
// ---------------------------------------------------------------------------
template <int MODE>
__global__ __launch_bounds__(256, 2) void gemm_k(
    const __nv_bfloat16* __restrict__ Ah, const __nv_bfloat16* __restrict__ Al,
    const __nv_bfloat16* __restrict__ Bh, const __nv_bfloat16* __restrict__ Bl,
    const float* __restrict__ bias, const float* __restrict__ rZ,
    float* __restrict__ Cf, __nv_bfloat16* __restrict__ Ch,
    __nv_bfloat16* __restrict__ Cl, int Kchunks, int zbase)
{
    extern __shared__ __align__(1024) char smem[];
    const uint32_t sbase = s2u(smem);
    const int tid = threadIdx.x;
    const int wid = tid >> 5, lane = tid & 31;
    const int m0 = blockIdx.y * 128, n0 = blockIdx.x * 128;
    const int z = blockIdx.z + zbase;
    const int zb = z >> 4, zh = z & 15;

    size_t a_base, b_base;
    int a_str, b_str;
    if (MODE == 2) {
        a_base = (size_t)m0 * 2048 + zb * 1024 + zh * 64; a_str = 2048;
        b_base = (size_t)n0 * 2048 + zb * 1024 + zh * 64; b_str = 2048;
    } else if (MODE == 3) {
        a_base = ((size_t)z << 20) + (size_t)m0 * 1024; a_str = 1024;
        b_base = (size_t)z * 262144 + (size_t)n0 * 1024; b_str = 1024;
    } else if (MODE == 4) {
        a_base = ((size_t)zbase * 4096 + m0) * 1024; a_str = 1024;
        b_base = (size_t)n0 * 1024; b_str = 1024;
    } else {  // MODE 1: vproj
        a_base = (size_t)m0 * 1024; a_str = 1024;
        b_base = (size_t)n0 * 1024; b_str = 1024;
    }

    const int wm = (wid >> 2) * 64, wn = (wid & 3) * 32;

    float acc[4][4][4];
#pragma unroll
    for (int i = 0; i < 4; i++)
#pragma unroll
        for (int j = 0; j < 4; j++)
#pragma unroll
            for (int e = 0; e < 4; e++) acc[i][j][e] = 0.f;

    gemm_core(Ah, Al, Bh, Bl, a_base, a_str, b_base, b_str,
              Kchunks, sbase, tid, wm, wn, acc);

    const int tr = lane >> 2, tc2 = (lane & 3) * 2;
#pragma unroll
    for (int mi = 0; mi < 4; mi++) {
#pragma unroll
        for (int nj = 0; nj < 4; nj++) {
            int n = n0 + wn + 8 * nj + tc2;
#pragma unroll
            for (int hr = 0; hr < 2; hr++) {
                int m = m0 + wm + 16 * mi + tr + hr * 8;
                float v0 = acc[mi][nj][hr * 2 + 0];
                float v1 = acc[mi][nj][hr * 2 + 1];
                if (MODE == 2) {
                    *(float2*)(Cf + ((size_t)z << 20) + (size_t)m * 1024 + n) =
                        make_float2(v0, v1);
                } else if (MODE == 3) {
                    int g = n >> 6, d = n & 63;
                    float rz = rZ[z * 4096 + g * 1024 + m];
                    float y0 = v0 * rz, y1 = v1 * rz;
                    float h0 = bhi(y0), h1 = bhi(y1);
                    size_t o = ((((size_t)zb * 4096 + g * 1024 + m) << 10)
                                + zh * 64 + d) >> 1;
                    ((uint32_t*)Ch)[o] = pk2(h0, h1);
                    ((uint32_t*)Cl)[o] = pk2(y0 - h0, y1 - h1);
                } else if (MODE == 4) {
                    __stcs((float2*)(Cf + ((size_t)(2 * m + zbase) << 10) + n),
                           make_float2(v0 + bias[n], v1 + bias[n + 1]));
                } else {  // MODE 1
                    *(float2*)(Cf + (size_t)m * 1024 + n) =
                        make_float2(v0 + bias[n], v1 + bias[n + 1]);
                }
            }
        }
    }
}

// ---------------------------------------------------------------------------
// K3: softmax — warp-per-row, row in registers; streaming hints
// ---------------------------------------------------------------------------
__global__ __launch_bounds__(256) void softmax_kernel(
    const float* __restrict__ qk, const float* __restrict__ emg,
    float* __restrict__ prob_out,
    __nv_bfloat16* __restrict__ Eh, __nv_bfloat16* __restrict__ El,
    float* __restrict__ rZg, int bh_base)
{
    __shared__ __align__(16) float em[4][1024];

    const int tid = threadIdx.x, wid = tid >> 5, lane = tid & 31;
    const int bh = blockIdx.y + bh_base, b = bh >> 4;
    const int t = blockIdx.x * 8 + wid;

    for (int i = tid; i < 1024; i += 256)
        ((float4*)&em[0][0])[i] = ((const float4*)(emg + b * 4096))[i];
    __syncthreads();

    const float* row = qk + ((size_t)bh << 20) + (size_t)t * 1024;
    float e[32];
#pragma unroll
    for (int j = 0; j < 8; j++) {
        float4 v = __ldcs((const float4*)(row + j * 128 + lane * 4));
        e[4 * j] = v.x; e[4 * j + 1] = v.y; e[4 * j + 2] = v.z; e[4 * j + 3] = v.w;
    }

    float mx = -1e30f;
#pragma unroll
    for (int i = 0; i < 32; i++) mx = fmaxf(mx, e[i]);
#pragma unroll
    for (int o = 16; o; o >>= 1) mx = fmaxf(mx, __shfl_xor_sync(0xffffffffu, mx, o));

#pragma unroll
    for (int i = 0; i < 32; i++) e[i] = __expf(e[i] - mx);

    float z[4] = {0.f, 0.f, 0.f, 0.f};
#pragma unroll
    for (int g = 0; g < 4; g++) {
#pragma unroll
        for (int j = 0; j < 8; j++) {
            float4 m = *(const float4*)&em[g][j * 128 + lane * 4];
            z[g] = fmaf(e[4 * j], m.x, z[g]);
            z[g] = fmaf(e[4 * j + 1], m.y, z[g]);
            z[g] = fmaf(e[4 * j + 2], m.z, z[g]);
            z[g] = fmaf(e[4 * j + 3], m.w, z[g]);
        }
    }
#pragma unroll
    for (int o = 16; o; o >>= 1) {
#pragma unroll
        for (int g = 0; g < 4; g++)
            z[g] += __shfl_xor_sync(0xffffffffu, z[g], o);
    }
    float rz[4];
#pragma unroll
    for (int g = 0; g < 4; g++) rz[g] = 1.f / z[g];
    if (lane < 4) rZg[bh * 4096 + lane * 1024 + t] = rz[lane];

    const size_t ebase = ((size_t)bh << 20) + (size_t)t * 1024;
#pragma unroll
    for (int j = 0; j < 8; j++) {
        float h0 = bhi(e[4 * j]), h1 = bhi(e[4 * j + 1]);
        float h2 = bhi(e[4 * j + 2]), h3 = bhi(e[4 * j + 3]);
        size_t o = (ebase + j * 128 + lane * 4) >> 2;
        ((uint2*)Eh)[o] = make_uint2(pk2(h0, h1), pk2(h2, h3));
        ((uint2*)El)[o] = make_uint2(pk2(e[4 * j] - h0, e[4 * j + 1] - h1),
                                     pk2(e[4 * j + 2] - h2, e[4 * j + 3] - h3));
    }

#pragma unroll
    for (int g = 0; g < 4; g++) {
        float* pout = prob_out + (((size_t)(bh * 4 + g) << 10) + t) * 1024;
        float rzg = rz[g];
#pragma unroll
        for (int j = 0; j < 8; j++) {
            float4 m = *(const float4*)&em[g][j * 128 + lane * 4];
            float4 o;
            o.x = e[4 * j] * m.x * rzg;
            o.y = e[4 * j + 1] * m.y * rzg;
            o.z = e[4 * j + 2] * m.z * rzg;
            o.w = e[4 * j + 3] * m.w * rzg;
            __stcs((float4*)(pout + j * 128 + lane * 4), o);
        }
    }
}

// ---------------------------------------------------------------------------
// K3b: vgt[bh][(g*64+d)][s] = emg[b,g,s] * V[s,b,h,d]   (hi/lo bf16)
// ---------------------------------------------------------------------------
__global__ __launch_bounds__(256) void build_vg(
    const float* __restrict__ vp, const float* __restrict__ emg,
    __nv_bfloat16* __restrict__ vgh, __nv_bfloat16* __restrict__ vgl)
{
    __shared__ float vsm[64][65];
    __shared__ float em[4][64];
    const int bh = blockIdx.y, b = bh >> 4, h = bh & 15;
    const int s0 = blockIdx.x * 64;
    const int tid = threadIdx.x;

#pragma unroll
    for (int it = 0; it < 4; it++) {
        int j = it * 256 + tid;
        int r = j >> 4, c4 = (j & 15) * 4;
        float4 v = *(const float4*)(vp + (size_t)((s0 + r) * 2 + b) * 1024 + h * 64 + c4);
        vsm[r][c4] = v.x; vsm[r][c4 + 1] = v.y; vsm[r][c4 + 2] = v.z; vsm[r][c4 + 3] = v.w;
    }
    {
        int g = tid >> 6, si = tid & 63;
        em[g][si] = emg[b * 4096 + g * 1024 + s0 + si];
    }
    __syncthreads();

    const int w = tid >> 5, lane = tid & 31;
#pragma unroll 4
    for (int rr = 0; rr < 32; rr++) {
        int gd = rr * 8 + w;
        int g = gd >> 6, d = gd & 63;
        float v0 = em[g][lane * 2] * vsm[lane * 2][d];
        float v1 = em[g][lane * 2 + 1] * vsm[lane * 2 + 1][d];
        float h0 = bhi(v0), h1 = bhi(v1);
        size_t o = ((size_t)bh * 262144 + (size_t)gd * 1024 + s0 + lane * 2) >> 1;
        ((uint32_t*)vgh)[o] = pk2(h0, h1);
        ((uint32_t*)vgl)[o] = pk2(v0 - h0, v1 - h1);
    }
}

// ---------------------------------------------------------------------------
extern "C" void kernel_launch(void* const* d_in, const int* in_sizes, int n_in,
                              void* d_out, int out_size)
{
    const float* query = (const float*)d_in[0];
    const float* key   = (const float*)d_in[1];
    const unsigned char* kpm = (const unsigned char*)d_in[2];
    const float* gmask = (const float*)d_in[3];
    const float* Wq = (const float*)d_in[4];
    const float* bq = (const float*)d_in[5];
    const float* Wk = (const float*)d_in[6];
    const float* bk = (const float*)d_in[7];
    const float* Wv = (const float*)d_in[8];
    const float* bv = (const float*)d_in[9];
    const float* Wo = (const float*)d_in[10];
    const float* bo = (const float*)d_in[11];

    float* out_proj = (float*)d_out;
    float* prob_out = (float*)d_out + (size_t)4 * 1024 * 2 * 1024;

    __nv_bfloat16 *qin_h, *qin_l, *kin_h, *kin_l;
    __nv_bfloat16 *wq_h, *wq_l, *wk_h, *wk_l, *wv_h, *wv_l, *wo_h, *wo_l;
    __nv_bfloat16 *qp_h, *qp_l, *kp_h, *kp_l, *E_h, *E_l, *vgt_h, *vgt_l, *aO_h, *aO_l;
    float *vp, *qkbuf, *rZ, *emg;
    cudaGetSymbolAddress((void**)&qin_h, g_qin_h); cudaGetSymbolAddress((void**)&qin_l, g_qin_l);
    cudaGetSymbolAddress((void**)&kin_h, g_kin_h); cudaGetSymbolAddress((void**)&kin_l, g_kin_l);
    cudaGetSymbolAddress((void**)&wq_h, g_wq_h); cudaGetSymbolAddress((void**)&wq_l, g_wq_l);
    cudaGetSymbolAddress((void**)&wk_h, g_wk_h); cudaGetSymbolAddress((void**)&wk_l, g_wk_l);
    cudaGetSymbolAddress((void**)&wv_h, g_wv_h); cudaGetSymbolAddress((void**)&wv_l, g_wv_l);
    cudaGetSymbolAddress((void**)&wo_h, g_wo_h); cudaGetSymbolAddress((void**)&wo_l, g_wo_l);
    cudaGetSymbolAddress((void**)&qp_h, g_qp_h); cudaGetSymbolAddress((void**)&qp_l, g_qp_l);
    cudaGetSymbolAddress((void**)&kp_h, g_kp_h); cudaGetSymbolAddress((void**)&kp_l, g_kp_l);
    cudaGetSymbolAddress((void**)&vp, g_vp);
    cudaGetSymbolAddress((void**)&qkbuf, g_qk);
    cudaGetSymbolAddress((void**)&E_h, g_E_h); cudaGetSymbolAddress((void**)&E_l, g_E_l);
    cudaGetSymbolAddress((void**)&rZ, g_rZ);
    cudaGetSymbolAddress((void**)&emg, g_emg);
    cudaGetSymbolAddress((void**)&vgt_h, g_vgt_h); cudaGetSymbolAddress((void**)&vgt_l, g_vgt_l);
    cudaGetSymbolAddress((void**)&aO_h, g_aO_h); cudaGetSymbolAddress((void**)&aO_l, g_aO_l);

    cudaFuncSetAttribute(gemm_qkproj, cudaFuncAttributeMaxDynamicSharedMemorySize, GEMM_SMEM);
    cudaFuncSetAttribute(gemm_k<1>, cudaFuncAttributeMaxDynamicSharedMemorySize, GEMM_SMEM);
    cudaFuncSetAttribute(gemm_k<2>, cudaFuncAttributeMaxDynamicSharedMemorySize, GEMM_SMEM);
    cudaFuncSetAttribute(gemm_k<3>, cudaFuncAttributeMaxDynamicSharedMemorySize, GEMM_SMEM);
    cudaFuncSetAttribute(gemm_k<4>, cudaFuncAttributeMaxDynamicSharedMemorySize, GEMM_SMEM);

    static cudaStream_t s2 = nullptr;
    static cudaEvent_t evStart = nullptr, evPrep = nullptr, evQKp = nullptr,
                       evVg = nullptr, evJoin = nullptr;
    if (!s2) {
        cudaStreamCreateWithFlags(&s2, cudaStreamNonBlocking);
        cudaEventCreateWithFlags(&evStart, cudaEventDisableTiming);
        cudaEventCreateWithFlags(&evPrep, cudaEventDisableTiming);
        cudaEventCreateWithFlags(&evQKp, cudaEventDisableTiming);
        cudaEventCreateWithFlags(&evVg, cudaEventDisableTiming);
        cudaEventCreateWithFlags(&evJoin, cudaEventDisableTiming);
    }

    // fork at t=0: s2 runs input-only prep (Wo split + exp(mask) table)
    cudaEventRecord(evStart, 0);
    cudaStreamWaitEvent(s2, evStart, 0);
    split_one_kernel<<<1024, 256, 0, s2>>>(Wo, wo_h, wo_l);
    prep_em<<<32, 256, 0, s2>>>(gmask, kpm, emg);
    cudaEventRecord(evPrep, s2);

    // s0: split 5 tensors (incl. Wv) then QK projections only
    SplitArgs sa;
    sa.src[0] = query; sa.h[0] = qin_h; sa.l[0] = qin_l;
    sa.src[1] = key;   sa.h[1] = kin_h; sa.l[1] = kin_l;
    sa.src[2] = Wq;    sa.h[2] = wq_h;  sa.l[2] = wq_l;
    sa.src[3] = Wk;    sa.h[3] = wk_h;  sa.l[3] = wk_l;
    sa.src[4] = Wv;    sa.h[4] = wv_h;  sa.l[4] = wv_l;
    sa.end[0] = 524288; sa.end[1] = 1048576;
    sa.end[2] = 1310720; sa.end[3] = 1572864;
    sa.end[4] = 1835008;
    split_all_kernel<<<1835008 / 256, 256>>>(sa);

    QKVArgs qa;
    qa.qh = qin_h; qa.ql = qin_l; qa.kh = kin_h; qa.kl = kin_l;
    qa.wqh = wq_h; qa.wql = wq_l; qa.wkh = wk_h; qa.wkl = wk_l;
    qa.bq = bq; qa.bk = bk;
    qa.qph = qp_h; qa.qpl = qp_l; qa.kph = kp_h; qa.kpl = kp_l;
    gemm_qkproj<<<dim3(8, 16, 2), 256, GEMM_SMEM>>>(qa);
    cudaEventRecord(evQKp, 0);

    // s2: V projection (overlaps qk0/sm0) then build_vg, then half-1 chain
    cudaStreamWaitEvent(s2, evQKp, 0);
    gemm_k<1><<<dim3(8, 16, 1), 256, GEMM_SMEM, s2>>>(kin_h, kin_l, wv_h, wv_l,
        bv, nullptr, vp, nullptr, nullptr, 32, 0);
    build_vg<<<dim3(16, 32), 256, 0, s2>>>(vp, emg, vgt_h, vgt_l);
    cudaEventRecord(evVg, s2);
    gemm_k<2><<<dim3(8, 8, 16), 256, GEMM_SMEM, s2>>>(qp_h, qp_l, kp_h, kp_l,
        nullptr, nullptr, qkbuf, nullptr, nullptr, 2, 16);
    softmax_kernel<<<dim3(128, 16), 256, 0, s2>>>(qkbuf, emg, prob_out,
                                                  E_h, E_l, rZ, 16);
    gemm_k<3><<<dim3(2, 8, 16), 256, GEMM_SMEM, s2>>>(E_h, E_l, vgt_h, vgt_l,
        nullptr, rZ, nullptr, aO_h, aO_l, 32, 16);
    gemm_k<4><<<dim3(8, 32, 1), 256, GEMM_SMEM, s2>>>(aO_h, aO_l, wo_h, wo_l,
        bo, nullptr, out_proj, nullptr, nullptr, 32, 1);
    cudaEventRecord(evJoin, s2);

    // s0: half-0 chain (needs emg for softmax; Wo for oproj0 — wait evPrep)
    cudaStreamWaitEvent(0, evPrep, 0);
    gemm_k<2><<<dim3(8, 8, 16), 256, GEMM_SMEM>>>(qp_h, qp_l, kp_h, kp_l,
        nullptr, nullptr, qkbuf, nullptr, nullptr, 2, 0);
    softmax_kernel<<<dim3(128, 16), 256>>>(qkbuf, emg, prob_out, E_h, E_l,
                                           rZ, 0);
    cudaStreamWaitEvent(0, evVg, 0);
    gemm_k<3><<<dim3(2, 8, 16), 256, GEMM_SMEM>>>(E_h, E_l, vgt_h, vgt_l,
        nullptr, rZ, nullptr, aO_h, aO_l, 32, 0);
    gemm_k<4><<<dim3(8, 32, 1), 256, GEMM_SMEM>>>(aO_h, aO_l, wo_h, wo_l,
        bo, nullptr, out_proj, nullptr, nullptr, 32, 0);

    // join
    cudaStreamWaitEvent(0, evJoin, 0);
}

// round 12
// speedup vs baseline: 1.0718x; 1.0718x over previous
#include <cuda_runtime.h>
#include <cuda_bf16.h>
#include <cstdint>

#define SCALING 0.125f

// ---------------------------------------------------------------------------
// helpers
// ---------------------------------------------------------------------------
__device__ __forceinline__ uint32_t s2u(const void* p) {
    uint32_t a;
    asm("{ .reg .u64 t; cvta.to.shared.u64 t, %1; cvt.u32.u64 %0, t; }"
        : "=r"(a) : "l"(p));
    return a;
}
__device__ __forceinline__ uint32_t pk2(float a, float b) {
    __nv_bfloat162 t = __floats2bfloat162_rn(a, b);
    return reinterpret_cast<uint32_t&>(t);
}
__device__ __forceinline__ float bhi(float x) {
    return __bfloat162float(__float2bfloat16(x));
}
__device__ __forceinline__ void ldsm4(uint32_t* r, uint32_t addr) {
    asm volatile("ldmatrix.sync.aligned.m8n8.x4.shared.b16 {%0,%1,%2,%3}, [%4];"
        : "=r"(r[0]), "=r"(r[1]), "=r"(r[2]), "=r"(r[3]) : "r"(addr));
}
__device__ __forceinline__ void mma_bf16(float* c, const uint32_t* a, const uint32_t* b) {
    asm volatile(
        "mma.sync.aligned.m16n8k16.row.col.f32.bf16.bf16.f32 "
        "{%0,%1,%2,%3}, {%4,%5,%6,%7}, {%8,%9}, {%0,%1,%2,%3};"
        : "+f"(c[0]), "+f"(c[1]), "+f"(c[2]), "+f"(c[3])
        : "r"(a[0]), "r"(a[1]), "r"(a[2]), "r"(a[3]), "r"(b[0]), "r"(b[1]));
}
#define SWZ(x) ((x) ^ (((x) >> 3) & 0x70))

#define CP_ASYNC16(dst, src) \
    asm volatile("cp.async.cg.shared.global [%0], [%1], 16;" :: "r"(dst), "l"(src))
#define CP_COMMIT() asm volatile("cp.async.commit_group;")
#define CP_WAIT0()  asm volatile("cp.async.wait_group 0;")
#define CP_WAIT1()  asm volatile("cp.async.wait_group 1;")

// ---------------------------------------------------------------------------
// Device scratch
// ---------------------------------------------------------------------------
__device__ __align__(16) __nv_bfloat16 g_qin_h[2048 * 1024], g_qin_l[2048 * 1024];
__device__ __align__(16) __nv_bfloat16 g_kin_h[2048 * 1024], g_kin_l[2048 * 1024];
__device__ __align__(16) __nv_bfloat16 g_wq_h[1024 * 1024], g_wq_l[1024 * 1024];
__device__ __align__(16) __nv_bfloat16 g_wk_h[1024 * 1024], g_wk_l[1024 * 1024];
__device__ __align__(16) __nv_bfloat16 g_wv_h[1024 * 1024], g_wv_l[1024 * 1024];
__device__ __align__(16) __nv_bfloat16 g_wo_h[1024 * 1024], g_wo_l[1024 * 1024];
__device__ __align__(16) __nv_bfloat16 g_qp_h[2048 * 1024], g_qp_l[2048 * 1024];
__device__ __align__(16) __nv_bfloat16 g_kp_h[2048 * 1024], g_kp_l[2048 * 1024];
__device__ __align__(16) float g_vp[2048 * 1024];
__device__ __align__(16) float g_qk[(size_t)32 * 1024 * 1024];
__device__ __align__(16) __nv_bfloat16 g_E_h[(size_t)32 * 1024 * 1024];
__device__ __align__(16) __nv_bfloat16 g_E_l[(size_t)32 * 1024 * 1024];
__device__ __align__(16) float g_rZ[32 * 4 * 1024];
__device__ __align__(16) float g_emg[2 * 4 * 1024];
__device__ __align__(16) __nv_bfloat16 g_vgt_h[32 * 256 * 1024], g_vgt_l[32 * 256 * 1024];
// attO layout: [b][g][t][d]
__device__ __align__(16) __nv_bfloat16 g_aO_h[8192 * 1024], g_aO_l[8192 * 1024];

// ---------------------------------------------------------------------------
// K0: fused fp32 -> bf16 hi/lo split over all 6 tensors in one launch
// ---------------------------------------------------------------------------
struct SplitArgs {
    const float* src[6];
    __nv_bfloat16* h[6];
    __nv_bfloat16* l[6];
    int end[6];
};

__global__ __launch_bounds__(256) void split_all_kernel(SplitArgs args)
{
    int i = blockIdx.x * 256 + threadIdx.x;
    int reg = 0;
#pragma unroll
    for (int r = 0; r < 5; r++) reg += (i >= args.end[r]) ? 1 : 0;
    int base = (reg == 0) ? 0 : args.end[reg - 1];
    int j = i - base;
    float4 v = ((const float4*)args.src[reg])[j];
    float h0 = bhi(v.x), h1 = bhi(v.y), h2 = bhi(v.z), h3 = bhi(v.w);
    ((uint2*)args.h[reg])[j] = make_uint2(pk2(h0, h1), pk2(h2, h3));
    ((uint2*)args.l[reg])[j] =
        make_uint2(pk2(v.x - h0, v.y - h1), pk2(v.z - h2, v.w - h3));
}

// ---------------------------------------------------------------------------
// prep: emg[b][g][s] = exp(gmask[b,g,s]) masked
// ---------------------------------------------------------------------------
__global__ __launch_bounds__(256) void prep_em(
    const float* __restrict__ gmask, const unsigned char* __restrict__ kpm,
    float* __restrict__ emg)
{
    int i = blockIdx.x * 256 + threadIdx.x;
    int b = i >> 12, s = i & 1023;
    float e = __expf(gmask[i]);
    if (kpm[b * 1024 + s]) e = 0.f;
    emg[i] = e;
}

// ---------------------------------------------------------------------------
// GEMM core: bf16x3 mma.sync, cp.async 3-stage, BK=32, ONE sync per chunk
// ---------------------------------------------------------------------------
#define GEMM_SMEM 98304

__device__ __forceinline__ void gemm_core(
    const __nv_bfloat16* __restrict__ Ah, const __nv_bfloat16* __restrict__ Al,
    const __nv_bfloat16* __restrict__ Bh, const __nv_bfloat16* __restrict__ Bl,
    size_t a_base, int a_str, size_t b_base, int b_str,
    int Kchunks, uint32_t sbase, int tid, int wm, int wn,
    float acc[4][4][4])
{
    const int lane = tid & 31;
    const int a_r  = lane & 15;
    const int a_kb = (lane >> 4) * 16;
    const int b_r  = (lane & 7) + ((lane >> 4) & 1) * 8;
    const int b_kb = ((lane >> 3) & 1) * 16;

#define ISSUE(kc, st) do {                                                     \
    const int _k0 = (kc) * 32;                                                 \
    _Pragma("unroll")                                                          \
    for (int it = 0; it < 8; it++) {                                           \
        int j = it * 256 + tid;                                                \
        int buf = j >> 10;                                                     \
        int r = (j >> 3) & 127;                                                \
        int ch = j & 7;                                                        \
        const __nv_bfloat16* src = buf ? (ch < 4 ? Bh : Bl)                    \
                                       : (ch < 4 ? Ah : Al);                   \
        size_t bs = buf ? b_base : a_base;                                     \
        int strd = buf ? b_str : a_str;                                        \
        uint32_t d = sbase + (st) * 32768 + buf * 16384 + SWZ(r * 128 + ch * 16);\
        CP_ASYNC16(d, src + bs + _k0 + (size_t)r * strd + (ch & 3) * 8);       \
    }                                                                          \
    CP_COMMIT();                                                               \
} while (0)

    ISSUE(0, 0);
    if (Kchunks > 1) ISSUE(1, 1);

    for (int kc = 0; kc < Kchunks; kc++) {
        const int st = kc % 3;
        if (kc + 1 < Kchunks) {
            CP_WAIT1();
        } else {
            CP_WAIT0();
        }
        __syncthreads();
        // safe: all warps completed compute(kc-1); stage (kc+2)%3 == (kc-1)%3
        if (kc + 2 < Kchunks) ISSUE(kc + 2, (kc + 2) % 3);

        const uint32_t sA = sbase + st * 32768;
        const uint32_t sB = sA + 16384;

#pragma unroll
        for (int ks = 0; ks < 2; ks++) {
            const int kbb = ks * 32;
            uint32_t ah[4][4], bb[2][4];
#pragma unroll
            for (int mi = 0; mi < 4; mi++)
                ldsm4(ah[mi], sA + SWZ((wm + 16 * mi + a_r) * 128 + kbb + a_kb));
#pragma unroll
            for (int jj = 0; jj < 2; jj++)
                ldsm4(bb[jj], sB + SWZ((wn + 16 * jj + b_r) * 128 + kbb + b_kb));
#pragma unroll
            for (int mi = 0; mi < 4; mi++)
#pragma unroll
                for (int nj = 0; nj < 4; nj++)
                    mma_bf16(acc[mi][nj], ah[mi], &bb[nj >> 1][(nj & 1) * 2]);
#pragma unroll
            for (int mi = 0; mi < 4; mi++) {
                uint32_t al[4];
                ldsm4(al, sA + SWZ((wm + 16 * mi + a_r) * 128 + 64 + kbb + a_kb));
#pragma unroll
                for (int nj = 0; nj < 4; nj++)
                    mma_bf16(acc[mi][nj], al, &bb[nj >> 1][(nj & 1) * 2]);
            }
#pragma unroll
            for (int jj = 0; jj < 2; jj++)
                ldsm4(bb[jj], sB + SWZ((wn + 16 * jj + b_r) * 128 + 64 + kbb + b_kb));
#pragma unroll
            for (int mi = 0; mi < 4; mi++)
#pragma unroll
                for (int nj = 0; nj < 4; nj++)
                    mma_bf16(acc[mi][nj], ah[mi], &bb[nj >> 1][(nj & 1) * 2]);
        }
    }
#undef ISSUE
}

// ---------------------------------------------------------------------------
// fused Q/K/V projection GEMM: z = 0:Q, 1:K, 2:V
// ---------------------------------------------------------------------------
struct QKVArgs {
    const __nv_bfloat16 *qh, *ql, *kh, *kl;
    const __nv_bfloat16 *wqh, *wql, *wkh, *wkl, *wvh, *wvl;
    const float *bq, *bk, *bv;
    __nv_bfloat16 *qph, *qpl, *kph, *kpl;
    float *vp;
};

__global__ __launch_bounds__(256, 2) void gemm_qkv(QKVArgs a)
{
    extern __shared__ __align__(1024) char smem[];
    const uint32_t sbase = s2u(smem);
    const int tid = threadIdx.x;
    const int wid = tid >> 5, lane = tid & 31;
    const int m0 = blockIdx.y * 128, n0 = blockIdx.x * 128;
    const int z = blockIdx.z;

    const __nv_bfloat16* Ah = (z == 0) ? a.qh : a.kh;
    const __nv_bfloat16* Al = (z == 0) ? a.ql : a.kl;
    const __nv_bfloat16* Bh = (z == 0) ? a.wqh : (z == 1) ? a.wkh : a.wvh;
    const __nv_bfloat16* Bl = (z == 0) ? a.wql : (z == 1) ? a.wkl : a.wvl;
    const float* bias = (z == 0) ? a.bq : (z == 1) ? a.bk : a.bv;
    const float scale = (z == 0) ? SCALING : 1.0f;

    const int wm = (wid >> 2) * 64, wn = (wid & 3) * 32;

    float acc[4][4][4];
#pragma unroll
    for (int i = 0; i < 4; i++)
#pragma unroll
        for (int j = 0; j < 4; j++)
#pragma unroll
            for (int e = 0; e < 4; e++) acc[i][j][e] = 0.f;

    gemm_core(Ah, Al, Bh, Bl, (size_t)m0 * 1024, 1024, (size_t)n0 * 1024, 1024,
              32, sbase, tid, wm, wn, acc);

    const int tr = lane >> 2, tc2 = (lane & 3) * 2;
#pragma unroll
    for (int mi = 0; mi < 4; mi++) {
#pragma unroll
        for (int nj = 0; nj < 4; nj++) {
            int n = n0 + wn + 8 * nj + tc2;
#pragma unroll
            for (int hr = 0; hr < 2; hr++) {
                int m = m0 + wm + 16 * mi + tr + hr * 8;
                float v0 = acc[mi][nj][hr * 2 + 0];
                float v1 = acc[mi][nj][hr * 2 + 1];
                if (z < 2) {
                    float y0 = (v0 + bias[n]) * scale, y1 = (v1 + bias[n + 1]) * scale;
                    float h0 = bhi(y0), h1 = bhi(y1);
                    size_t o = ((size_t)m * 1024 + n) >> 1;
                    __nv_bfloat16* Ch = (z == 0) ? a.qph : a.kph;
                    __nv_bfloat16* Cl = (z == 0) ? a.qpl : a.kpl;
                    ((uint32_t*)Ch)[o] = pk2(h0, h1);
                    ((uint32_t*)Cl)[o] = pk2(y0 - h0, y1 - h1);
                } else {
                    *(float2*)(a.vp + (size_t)m * 1024 + n) =
                        make_float2(v0 + bias[n], v1 + bias[n + 1]);
                }
            }
        }
    }
}

// ---------------------------------------------------------------------------
// generic GEMM: MODE 2 qk, 3 pv, 4 oproj
// MODE 2/3: zbase = bh offset.  MODE 4: zbase = b (half), M = 4096 rows.
// ---------------------------------------------------------------------------
template <int MODE>
__global__ __launch_bounds__(256, 2) void gemm_k(
    const __nv_bfloat16* __restrict__ Ah, const __nv_bfloat16* __restrict__ Al,
    const __nv_bfloat16* __restrict__ Bh, const __nv_bfloat16* __restrict__ Bl,
    const float* __restrict__ bias, const float* __restrict__ rZ,
    float* __restrict__ Cf, __nv_bfloat16* __restrict__ Ch,
    __nv_bfloat16* __restrict__ Cl, int Kchunks, int zbase)
{
    extern __shared__ __align__(1024) char smem[];
    const uint32_t sbase = s2u(smem);
    const int tid = threadIdx.x;
    const int wid = tid >> 5, lane = tid & 31;
    const int m0 = blockIdx.y * 128, n0 = blockIdx.x * 128;
    const int z = blockIdx.z + zbase;
    const int zb = z >> 4, zh = z & 15;

    size_t a_base, b_base;
    int a_str, b_str;
    if (MODE == 2) {
        a_base = (size_t)m0 * 2048 + zb * 1024 + zh * 64; a_str = 2048;
        b_base = (size_t)n0 * 2048 + zb * 1024 + zh * 64; b_str = 2048;
    } else if (MODE == 3) {
        a_base = ((size_t)z << 20) + (size_t)m0 * 1024; a_str = 1024;
        b_base = (size_t)z * 262144 + (size_t)n0 * 1024; b_str = 1024;
    } else {
        a_base = ((size_t)zbase * 4096 + m0) * 1024; a_str = 1024;
        b_base = (size_t)n0 * 1024; b_str = 1024;
    }

    const int wm = (wid >> 2) * 64, wn = (wid & 3) * 32;

    float acc[4][4][4];
#pragma unroll
    for (int i = 0; i < 4; i++)
#pragma unroll
        for (int j = 0; j < 4; j++)
#pragma unroll
            for (int e = 0; e < 4; e++) acc[i][j][e] = 0.f;

    gemm_core(Ah, Al, Bh, Bl, a_base, a_str, b_base, b_str,
              Kchunks, sbase, tid, wm, wn, acc);

    const int tr = lane >> 2, tc2 = (lane & 3) * 2;
#pragma unroll
    for (int mi = 0; mi < 4; mi++) {
#pragma unroll
        for (int nj = 0; nj < 4; nj++) {
            int n = n0 + wn + 8 * nj + tc2;
#pragma unroll
            for (int hr = 0; hr < 2; hr++) {
                int m = m0 + wm + 16 * mi + tr + hr * 8;
                float v0 = acc[mi][nj][hr * 2 + 0];
                float v1 = acc[mi][nj][hr * 2 + 1];
                if (MODE == 2) {
                    *(float2*)(Cf + ((size_t)z << 20) + (size_t)m * 1024 + n) =
                        make_float2(v0, v1);
                } else if (MODE == 3) {
                    int g = n >> 6, d = n & 63;
                    float rz = rZ[z * 4096 + g * 1024 + m];
                    float y0 = v0 * rz, y1 = v1 * rz;
                    float h0 = bhi(y0), h1 = bhi(y1);
                    size_t o = ((((size_t)zb * 4096 + g * 1024 + m) << 10)
                                + zh * 64 + d) >> 1;
                    ((uint32_t*)Ch)[o] = pk2(h0, h1);
                    ((uint32_t*)Cl)[o] = pk2(y0 - h0, y1 - h1);
                } else {
                    __stcs((float2*)(Cf + ((size_t)(2 * m + zbase) << 10) + n),
                           make_float2(v0 + bias[n], v1 + bias[n + 1]));
                }
            }
        }
    }
}

// ---------------------------------------------------------------------------
// K3: softmax — warp-per-row, row in registers; streaming hints
// ---------------------------------------------------------------------------
__global__ __launch_bounds__(256) void softmax_kernel(
    const float* __restrict__ qk, const float* __restrict__ emg,
    float* __restrict__ prob_out,
    __nv_bfloat16* __restrict__ Eh, __nv_bfloat16* __restrict__ El,
    float* __restrict__ rZg, int bh_base)
{
    __shared__ __align__(16) float em[4][1024];

    const int tid = threadIdx.x, wid = tid >> 5, lane = tid & 31;
    const int bh = blockIdx.y + bh_base, b = bh >> 4;
    const int t = blockIdx.x * 8 + wid;

    for (int i = tid; i < 1024; i += 256)
        ((float4*)&em[0][0])[i] = ((const float4*)(emg + b * 4096))[i];
    __syncthreads();

    const float* row = qk + ((size_t)bh << 20) + (size_t)t * 1024;
    float e[32];
#pragma unroll
    for (int j = 0; j < 8; j++) {
        float4 v = __ldcs((const float4*)(row + j * 128 + lane * 4));
        e[4 * j] = v.x; e[4 * j + 1] = v.y; e[4 * j + 2] = v.z; e[4 * j + 3] = v.w;
    }

    float mx = -1e30f;
#pragma unroll
    for (int i = 0; i < 32; i++) mx = fmaxf(mx, e[i]);
#pragma unroll
    for (int o = 16; o; o >>= 1) mx = fmaxf(mx, __shfl_xor_sync(0xffffffffu, mx, o));

#pragma unroll
    for (int i = 0; i < 32; i++) e[i] = __expf(e[i] - mx);

    float z[4] = {0.f, 0.f, 0.f, 0.f};
#pragma unroll
    for (int g = 0; g < 4; g++) {
#pragma unroll
        for (int j = 0; j < 8; j++) {
            float4 m = *(const float4*)&em[g][j * 128 + lane * 4];
            z[g] = fmaf(e[4 * j], m.x, z[g]);
            z[g] = fmaf(e[4 * j + 1], m.y, z[g]);
            z[g] = fmaf(e[4 * j + 2], m.z, z[g]);
            z[g] = fmaf(e[4 * j + 3], m.w, z[g]);
        }
    }
#pragma unroll
    for (int o = 16; o; o >>= 1) {
#pragma unroll
        for (int g = 0; g < 4; g++)
            z[g] += __shfl_xor_sync(0xffffffffu, z[g], o);
    }
    float rz[4];
#pragma unroll
    for (int g = 0; g < 4; g++) rz[g] = 1.f / z[g];
    if (lane < 4) rZg[bh * 4096 + lane * 1024 + t] = rz[lane];

    const size_t ebase = ((size_t)bh << 20) + (size_t)t * 1024;
#pragma unroll
    for (int j = 0; j < 8; j++) {
        float h0 = bhi(e[4 * j]), h1 = bhi(e[4 * j + 1]);
        float h2 = bhi(e[4 * j + 2]), h3 = bhi(e[4 * j + 3]);
        size_t o = (ebase + j * 128 + lane * 4) >> 2;
        ((uint2*)Eh)[o] = make_uint2(pk2(h0, h1), pk2(h2, h3));
        ((uint2*)El)[o] = make_uint2(pk2(e[4 * j] - h0, e[4 * j + 1] - h1),
                                     pk2(e[4 * j + 2] - h2, e[4 * j + 3] - h3));
    }

#pragma unroll
    for (int g = 0; g < 4; g++) {
        float* pout = prob_out + (((size_t)(bh * 4 + g) << 10) + t) * 1024;
        float rzg = rz[g];
#pragma unroll
        for (int j = 0; j < 8; j++) {
            float4 m = *(const float4*)&em[g][j * 128 + lane * 4];
            float4 o;
            o.x = e[4 * j] * m.x * rzg;
            o.y = e[4 * j + 1] * m.y * rzg;
            o.z = e[4 * j + 2] * m.z * rzg;
            o.w = e[4 * j + 3] * m.w * rzg;
            __stcs((float4*)(pout + j * 128 + lane * 4), o);
        }
    }
}

// ---------------------------------------------------------------------------
// K3b: vgt[bh][(g*64+d)][s] = emg[b,g,s] * V[s,b,h,d]   (hi/lo bf16)
// ---------------------------------------------------------------------------
__global__ __launch_bounds__(256) void build_vg(
    const float* __restrict__ vp, const float* __restrict__ emg,
    __nv_bfloat16* __restrict__ vgh, __nv_bfloat16* __restrict__ vgl)
{
    __shared__ float vsm[64][65];
    __shared__ float em[4][64];
    const int bh = blockIdx.y, b = bh >> 4, h = bh & 15;
    const int s0 = blockIdx.x * 64;
    const int tid = threadIdx.x;

#pragma unroll
    for (int it = 0; it < 4; it++) {
        int j = it * 256 + tid;
        int r = j >> 4, c4 = (j & 15) * 4;
        float4 v = *(const float4*)(vp + (size_t)((s0 + r) * 2 + b) * 1024 + h * 64 + c4);
        vsm[r][c4] = v.x; vsm[r][c4 + 1] = v.y; vsm[r][c4 + 2] = v.z; vsm[r][c4 + 3] = v.w;
    }
    {
        int g = tid >> 6, si = tid & 63;
        em[g][si] = emg[b * 4096 + g * 1024 + s0 + si];
    }
    __syncthreads();

    const int w = tid >> 5, lane = tid & 31;
#pragma unroll 4
    for (int rr = 0; rr < 32; rr++) {
        int gd = rr * 8 + w;
        int g = gd >> 6, d = gd & 63;
        float v0 = em[g][lane * 2] * vsm[lane * 2][d];
        float v1 = em[g][lane * 2 + 1] * vsm[lane * 2 + 1][d];
        float h0 = bhi(v0), h1 = bhi(v1);
        size_t o = ((size_t)bh * 262144 + (size_t)gd * 1024 + s0 + lane * 2) >> 1;
        ((uint32_t*)vgh)[o] = pk2(h0, h1);
        ((uint32_t*)vgl)[o] = pk2(v0 - h0, v1 - h1);
    }
}

// ---------------------------------------------------------------------------
extern "C" void kernel_launch(void* const* d_in, const int* in_sizes, int n_in,
                              void* d_out, int out_size)
{
    const float* query = (const float*)d_in[0];
    const float* key   = (const float*)d_in[1];
    const unsigned char* kpm = (const unsigned char*)d_in[2];
    const float* gmask = (const float*)d_in[3];
    const float* Wq = (const float*)d_in[4];
    const float* bq = (const float*)d_in[5];
    const float* Wk = (const float*)d_in[6];
    const float* bk = (const float*)d_in[7];
    const float* Wv = (const float*)d_in[8];
    const float* bv = (const float*)d_in[9];
    const float* Wo = (const float*)d_in[10];
    const float* bo = (const float*)d_in[11];

    float* out_proj = (float*)d_out;
    float* prob_out = (float*)d_out + (size_t)4 * 1024 * 2 * 1024;

    __nv_bfloat16 *qin_h, *qin_l, *kin_h, *kin_l;
    __nv_bfloat16 *wq_h, *wq_l, *wk_h, *wk_l, *wv_h, *wv_l, *wo_h, *wo_l;
    __nv_bfloat16 *qp_h, *qp_l, *kp_h, *kp_l, *E_h, *E_l, *vgt_h, *vgt_l, *aO_h, *aO_l;
    float *vp, *qkbuf, *rZ, *emg;
    cudaGetSymbolAddress((void**)&qin_h, g_qin_h); cudaGetSymbolAddress((void**)&qin_l, g_qin_l);
    cudaGetSymbolAddress((void**)&kin_h, g_kin_h); cudaGetSymbolAddress((void**)&kin_l, g_kin_l);
    cudaGetSymbolAddress((void**)&wq_h, g_wq_h); cudaGetSymbolAddress((void**)&wq_l, g_wq_l);
    cudaGetSymbolAddress((void**)&wk_h, g_wk_h); cudaGetSymbolAddress((void**)&wk_l, g_wk_l);
    cudaGetSymbolAddress((void**)&wv_h, g_wv_h); cudaGetSymbolAddress((void**)&wv_l, g_wv_l);
    cudaGetSymbolAddress((void**)&wo_h, g_wo_h); cudaGetSymbolAddress((void**)&wo_l, g_wo_l);
    cudaGetSymbolAddress((void**)&qp_h, g_qp_h); cudaGetSymbolAddress((void**)&qp_l, g_qp_l);
    cudaGetSymbolAddress((void**)&kp_h, g_kp_h); cudaGetSymbolAddress((void**)&kp_l, g_kp_l);
    cudaGetSymbolAddress((void**)&vp, g_vp);
    cudaGetSymbolAddress((void**)&qkbuf, g_qk);
    cudaGetSymbolAddress((void**)&E_h, g_E_h); cudaGetSymbolAddress((void**)&E_l, g_E_l);
    cudaGetSymbolAddress((void**)&rZ, g_rZ);
    cudaGetSymbolAddress((void**)&emg, g_emg);
    cudaGetSymbolAddress((void**)&vgt_h, g_vgt_h); cudaGetSymbolAddress((void**)&vgt_l, g_vgt_l);
    cudaGetSymbolAddress((void**)&aO_h, g_aO_h); cudaGetSymbolAddress((void**)&aO_l, g_aO_l);

    cudaFuncSetAttribute(gemm_qkv, cudaFuncAttributeMaxDynamicSharedMemorySize, GEMM_SMEM);
    cudaFuncSetAttribute(gemm_k<2>, cudaFuncAttributeMaxDynamicSharedMemorySize, GEMM_SMEM);
    cudaFuncSetAttribute(gemm_k<3>, cudaFuncAttributeMaxDynamicSharedMemorySize, GEMM_SMEM);
    cudaFuncSetAttribute(gemm_k<4>, cudaFuncAttributeMaxDynamicSharedMemorySize, GEMM_SMEM);

    static cudaStream_t s2 = nullptr;
    static cudaEvent_t evFork = nullptr, evVg = nullptr, evJoin = nullptr;
    if (!s2) {
        cudaStreamCreateWithFlags(&s2, cudaStreamNonBlocking);
        cudaEventCreateWithFlags(&evFork, cudaEventDisableTiming);
        cudaEventCreateWithFlags(&evVg, cudaEventDisableTiming);
        cudaEventCreateWithFlags(&evJoin, cudaEventDisableTiming);
    }

    SplitArgs sa;
    sa.src[0] = query; sa.h[0] = qin_h; sa.l[0] = qin_l;
    sa.src[1] = key;   sa.h[1] = kin_h; sa.l[1] = kin_l;
    sa.src[2] = Wq;    sa.h[2] = wq_h;  sa.l[2] = wq_l;
    sa.src[3] = Wk;    sa.h[3] = wk_h;  sa.l[3] = wk_l;
    sa.src[4] = Wv;    sa.h[4] = wv_h;  sa.l[4] = wv_l;
    sa.src[5] = Wo;    sa.h[5] = wo_h;  sa.l[5] = wo_l;
    sa.end[0] = 524288; sa.end[1] = 1048576;
    sa.end[2] = 1310720; sa.end[3] = 1572864;
    sa.end[4] = 1835008; sa.end[5] = 2097152;
    split_all_kernel<<<2097152 / 256, 256>>>(sa);
    prep_em<<<32, 256>>>(gmask, kpm, emg);

    QKVArgs qa;
    qa.qh = qin_h; qa.ql = qin_l; qa.kh = kin_h; qa.kl = kin_l;
    qa.wqh = wq_h; qa.wql = wq_l; qa.wkh = wk_h; qa.wkl = wk_l;
    qa.wvh = wv_h; qa.wvl = wv_l;
    qa.bq = bq; qa.bk = bk; qa.bv = bv;
    qa.qph = qp_h; qa.qpl = qp_l; qa.kph = kp_h; qa.kpl = kp_l;
    qa.vp = vp;
    gemm_qkv<<<dim3(8, 16, 3), 256, GEMM_SMEM>>>(qa);

    // fork
    cudaEventRecord(evFork, 0);
    cudaStreamWaitEvent(s2, evFork, 0);

    // s2: build_vg then half-1 chain (b=1, bh 16..31) + oproj(b=1)
    build_vg<<<dim3(16, 32), 256, 0, s2>>>(vp, emg, vgt_h, vgt_l);
    cudaEventRecord(evVg, s2);
    gemm_k<2><<<dim3(8, 8, 16), 256, GEMM_SMEM, s2>>>(qp_h, qp_l, kp_h, kp_l,
        nullptr, nullptr, qkbuf, nullptr, nullptr, 2, 16);
    softmax_kernel<<<dim3(128, 16), 256, 0, s2>>>(qkbuf, emg, prob_out,
                                                  E_h, E_l, rZ, 16);
    gemm_k<3><<<dim3(2, 8, 16), 256, GEMM_SMEM, s2>>>(E_h, E_l, vgt_h, vgt_l,
        nullptr, rZ, nullptr, aO_h, aO_l, 32, 16);
    gemm_k<4><<<dim3(8, 32, 1), 256, GEMM_SMEM, s2>>>(aO_h, aO_l, wo_h, wo_l,
        bo, nullptr, out_proj, nullptr, nullptr, 32, 1);
    cudaEventRecord(evJoin, s2);

    // default stream: half-0 chain (b=0, bh 0..15) + oproj(b=0)
    gemm_k<2><<<dim3(8, 8, 16), 256, GEMM_SMEM>>>(qp_h, qp_l, kp_h, kp_l,
        nullptr, nullptr, qkbuf, nullptr, nullptr, 2, 0);
    softmax_kernel<<<dim3(128, 16), 256>>>(qkbuf, emg, prob_out, E_h, E_l,
                                           rZ, 0);
    cudaStreamWaitEvent(0, evVg, 0);
    gemm_k<3><<<dim3(2, 8, 16), 256, GEMM_SMEM>>>(E_h, E_l, vgt_h, vgt_l,
        nullptr, rZ, nullptr, aO_h, aO_l, 32, 0);
    gemm_k<4><<<dim3(8, 32, 1), 256, GEMM_SMEM>>>(aO_h, aO_l, wo_h, wo_l,
        bo, nullptr, out_proj, nullptr, nullptr, 32, 0);

    // join
    cudaStreamWaitEvent(0, evJoin, 0);
}

// round 13
// speedup vs baseline: 1.0782x; 1.0059x over previous
#include <cuda_runtime.h>
#include <cuda_bf16.h>
#include <cstdint>

#define SCALING 0.125f

// ---------------------------------------------------------------------------
// helpers
// ---------------------------------------------------------------------------
__device__ __forceinline__ uint32_t s2u(const void* p) {
    uint32_t a;
    asm("{ .reg .u64 t; cvta.to.shared.u64 t, %1; cvt.u32.u64 %0, t; }"
        : "=r"(a) : "l"(p));
    return a;
}
__device__ __forceinline__ uint32_t pk2(float a, float b) {
    __nv_bfloat162 t = __floats2bfloat162_rn(a, b);
    return reinterpret_cast<uint32_t&>(t);
}
__device__ __forceinline__ float bhi(float x) {
    return __bfloat162float(__float2bfloat16(x));
}
__device__ __forceinline__ float2 upk(uint32_t u) {
    __nv_bfloat162 t = reinterpret_cast<__nv_bfloat162&>(u);
    return make_float2(__bfloat162float(t.x), __bfloat162float(t.y));
}
__device__ __forceinline__ void ldsm4(uint32_t* r, uint32_t addr) {
    asm volatile("ldmatrix.sync.aligned.m8n8.x4.shared.b16 {%0,%1,%2,%3}, [%4];"
        : "=r"(r[0]), "=r"(r[1]), "=r"(r[2]), "=r"(r[3]) : "r"(addr));
}
__device__ __forceinline__ void mma_bf16(float* c, const uint32_t* a, const uint32_t* b) {
    asm volatile(
        "mma.sync.aligned.m16n8k16.row.col.f32.bf16.bf16.f32 "
        "{%0,%1,%2,%3}, {%4,%5,%6,%7}, {%8,%9}, {%0,%1,%2,%3};"
        : "+f"(c[0]), "+f"(c[1]), "+f"(c[2]), "+f"(c[3])
        : "r"(a[0]), "r"(a[1]), "r"(a[2]), "r"(a[3]), "r"(b[0]), "r"(b[1]));
}
#define SWZ(x) ((x) ^ (((x) >> 3) & 0x70))

#define CP_ASYNC16(dst, src) \
    asm volatile("cp.async.cg.shared.global [%0], [%1], 16;" :: "r"(dst), "l"(src))
#define CP_COMMIT() asm volatile("cp.async.commit_group;")
#define CP_WAIT0()  asm volatile("cp.async.wait_group 0;")
#define CP_WAIT1()  asm volatile("cp.async.wait_group 1;")

// ---------------------------------------------------------------------------
// Device scratch
// ---------------------------------------------------------------------------
__device__ __align__(16) __nv_bfloat16 g_qin_h[2048 * 1024], g_qin_l[2048 * 1024];
__device__ __align__(16) __nv_bfloat16 g_kin_h[2048 * 1024], g_kin_l[2048 * 1024];
__device__ __align__(16) __nv_bfloat16 g_wq_h[1024 * 1024], g_wq_l[1024 * 1024];
__device__ __align__(16) __nv_bfloat16 g_wk_h[1024 * 1024], g_wk_l[1024 * 1024];
__device__ __align__(16) __nv_bfloat16 g_wv_h[1024 * 1024], g_wv_l[1024 * 1024];
__device__ __align__(16) __nv_bfloat16 g_wo_h[1024 * 1024], g_wo_l[1024 * 1024];
__device__ __align__(16) __nv_bfloat16 g_qp_h[2048 * 1024], g_qp_l[2048 * 1024];
__device__ __align__(16) __nv_bfloat16 g_kp_h[2048 * 1024], g_kp_l[2048 * 1024];
__device__ __align__(16) float g_vp[2048 * 1024];
__device__ __align__(16) float g_zpart[32 * 8 * 1024 * 4];  // [z][sTile][t][g]
__device__ __align__(16) __nv_bfloat16 g_E_h[(size_t)32 * 1024 * 1024];
__device__ __align__(16) __nv_bfloat16 g_E_l[(size_t)32 * 1024 * 1024];
__device__ __align__(16) float g_rZ[32 * 4 * 1024];
__device__ __align__(16) float g_emg[2 * 4 * 1024];
__device__ __align__(16) __nv_bfloat16 g_vgt_h[32 * 256 * 1024], g_vgt_l[32 * 256 * 1024];
// attO layout: [b][g][t][d]
__device__ __align__(16) __nv_bfloat16 g_aO_h[8192 * 1024], g_aO_l[8192 * 1024];

// ---------------------------------------------------------------------------
// K0: fused fp32 -> bf16 hi/lo split over all 6 tensors in one launch
// ---------------------------------------------------------------------------
struct SplitArgs {
    const float* src[6];
    __nv_bfloat16* h[6];
    __nv_bfloat16* l[6];
    int end[6];
};

__global__ __launch_bounds__(256) void split_all_kernel(SplitArgs args)
{
    int i = blockIdx.x * 256 + threadIdx.x;
    int reg = 0;
#pragma unroll
    for (int r = 0; r < 5; r++) reg += (i >= args.end[r]) ? 1 : 0;
    int base = (reg == 0) ? 0 : args.end[reg - 1];
    int j = i - base;
    float4 v = ((const float4*)args.src[reg])[j];
    float h0 = bhi(v.x), h1 = bhi(v.y), h2 = bhi(v.z), h3 = bhi(v.w);
    ((uint2*)args.h[reg])[j] = make_uint2(pk2(h0, h1), pk2(h2, h3));
    ((uint2*)args.l[reg])[j] =
        make_uint2(pk2(v.x - h0, v.y - h1), pk2(v.z - h2, v.w - h3));
}

// ---------------------------------------------------------------------------
// prep: emg[b][g][s] = exp(gmask[b,g,s]) masked
// ---------------------------------------------------------------------------
__global__ __launch_bounds__(256) void prep_em(
    const float* __restrict__ gmask, const unsigned char* __restrict__ kpm,
    float* __restrict__ emg)
{
    int i = blockIdx.x * 256 + threadIdx.x;
    int b = i >> 12, s = i & 1023;
    float e = __expf(gmask[i]);
    if (kpm[b * 1024 + s]) e = 0.f;
    emg[i] = e;
}

// ---------------------------------------------------------------------------
// GEMM core: bf16x3 mma.sync, cp.async 3-stage, BK=32, one sync per chunk
// ---------------------------------------------------------------------------
#define GEMM_SMEM 98304

__device__ __forceinline__ void gemm_core(
    const __nv_bfloat16* __restrict__ Ah, const __nv_bfloat16* __restrict__ Al,
    const __nv_bfloat16* __restrict__ Bh, const __nv_bfloat16* __restrict__ Bl,
    size_t a_base, int a_str, size_t b_base, int b_str,
    int Kchunks, uint32_t sbase, int tid, int wm, int wn,
    float acc[4][4][4])
{
    const int lane = tid & 31;
    const int a_r  = lane & 15;
    const int a_kb = (lane >> 4) * 16;
    const int b_r  = (lane & 7) + ((lane >> 4) & 1) * 8;
    const int b_kb = ((lane >> 3) & 1) * 16;

#define ISSUE(kc, st) do {                                                     \
    const int _k0 = (kc) * 32;                                                 \
    _Pragma("unroll")                                                          \
    for (int it = 0; it < 8; it++) {                                           \
        int j = it * 256 + tid;                                                \
        int buf = j >> 10;                                                     \
        int r = (j >> 3) & 127;                                                \
        int ch = j & 7;                                                        \
        const __nv_bfloat16* src = buf ? (ch < 4 ? Bh : Bl)                    \
                                       : (ch < 4 ? Ah : Al);                   \
        size_t bs = buf ? b_base : a_base;                                     \
        int strd = buf ? b_str : a_str;                                        \
        uint32_t d = sbase + (st) * 32768 + buf * 16384 + SWZ(r * 128 + ch * 16);\
        CP_ASYNC16(d, src + bs + _k0 + (size_t)r * strd + (ch & 3) * 8);       \
    }                                                                          \
    CP_COMMIT();                                                               \
} while (0)

    ISSUE(0, 0);
    if (Kchunks > 1) ISSUE(1, 1);

    for (int kc = 0; kc < Kchunks; kc++) {
        const int st = kc % 3;
        if (kc + 1 < Kchunks) {
            CP_WAIT1();
        } else {
            CP_WAIT0();
        }
        __syncthreads();
        if (kc + 2 < Kchunks) ISSUE(kc + 2, (kc + 2) % 3);

        const uint32_t sA = sbase + st * 32768;
        const uint32_t sB = sA + 16384;

#pragma unroll
        for (int ks = 0; ks < 2; ks++) {
            const int kbb = ks * 32;
            uint32_t ah[4][4], bb[2][4];
#pragma unroll
            for (int mi = 0; mi < 4; mi++)
                ldsm4(ah[mi], sA + SWZ((wm + 16 * mi + a_r) * 128 + kbb + a_kb));
#pragma unroll
            for (int jj = 0; jj < 2; jj++)
                ldsm4(bb[jj], sB + SWZ((wn + 16 * jj + b_r) * 128 + kbb + b_kb));
#pragma unroll
            for (int mi = 0; mi < 4; mi++)
#pragma unroll
                for (int nj = 0; nj < 4; nj++)
                    mma_bf16(acc[mi][nj], ah[mi], &bb[nj >> 1][(nj & 1) * 2]);
#pragma unroll
            for (int mi = 0; mi < 4; mi++) {
                uint32_t al[4];
                ldsm4(al, sA + SWZ((wm + 16 * mi + a_r) * 128 + 64 + kbb + a_kb));
#pragma unroll
                for (int nj = 0; nj < 4; nj++)
                    mma_bf16(acc[mi][nj], al, &bb[nj >> 1][(nj & 1) * 2]);
            }
#pragma unroll
            for (int jj = 0; jj < 2; jj++)
                ldsm4(bb[jj], sB + SWZ((wn + 16 * jj + b_r) * 128 + 64 + kbb + b_kb));
#pragma unroll
            for (int mi = 0; mi < 4; mi++)
#pragma unroll
                for (int nj = 0; nj < 4; nj++)
                    mma_bf16(acc[mi][nj], ah[mi], &bb[nj >> 1][(nj & 1) * 2]);
        }
    }
#undef ISSUE
}

// ---------------------------------------------------------------------------
// fused Q/K/V projection GEMM: z = 0:Q, 1:K, 2:V
// ---------------------------------------------------------------------------
struct QKVArgs {
    const __nv_bfloat16 *qh, *ql, *kh, *kl;
    const __nv_bfloat16 *wqh, *wql, *wkh, *wkl, *wvh, *wvl;
    const float *bq, *bk, *bv;
    __nv_bfloat16 *qph, *qpl, *kph, *kpl;
    float *vp;
};

__global__ __launch_bounds__(256, 2) void gemm_qkv(QKVArgs a)
{
    extern __shared__ __align__(1024) char smem[];
    const uint32_t sbase = s2u(smem);
    const int tid = threadIdx.x;
    const int wid = tid >> 5, lane = tid & 31;
    const int m0 = blockIdx.y * 128, n0 = blockIdx.x * 128;
    const int z = blockIdx.z;

    const __nv_bfloat16* Ah = (z == 0) ? a.qh : a.kh;
    const __nv_bfloat16* Al = (z == 0) ? a.ql : a.kl;
    const __nv_bfloat16* Bh = (z == 0) ? a.wqh : (z == 1) ? a.wkh : a.wvh;
    const __nv_bfloat16* Bl = (z == 0) ? a.wql : (z == 1) ? a.wkl : a.wvl;
    const float* bias = (z == 0) ? a.bq : (z == 1) ? a.bk : a.bv;
    const float scale = (z == 0) ? SCALING : 1.0f;

    const int wm = (wid >> 2) * 64, wn = (wid & 3) * 32;

    float acc[4][4][4];
#pragma unroll
    for (int i = 0; i < 4; i++)
#pragma unroll
        for (int j = 0; j < 4; j++)
#pragma unroll
            for (int e = 0; e < 4; e++) acc[i][j][e] = 0.f;

    gemm_core(Ah, Al, Bh, Bl, (size_t)m0 * 1024, 1024, (size_t)n0 * 1024, 1024,
              32, sbase, tid, wm, wn, acc);

    const int tr = lane >> 2, tc2 = (lane & 3) * 2;
#pragma unroll
    for (int mi = 0; mi < 4; mi++) {
#pragma unroll
        for (int nj = 0; nj < 4; nj++) {
            int n = n0 + wn + 8 * nj + tc2;
#pragma unroll
            for (int hr = 0; hr < 2; hr++) {
                int m = m0 + wm + 16 * mi + tr + hr * 8;
                float v0 = acc[mi][nj][hr * 2 + 0];
                float v1 = acc[mi][nj][hr * 2 + 1];
                if (z < 2) {
                    float y0 = (v0 + bias[n]) * scale, y1 = (v1 + bias[n + 1]) * scale;
                    float h0 = bhi(y0), h1 = bhi(y1);
                    size_t o = ((size_t)m * 1024 + n) >> 1;
                    __nv_bfloat16* Ch = (z == 0) ? a.qph : a.kph;
                    __nv_bfloat16* Cl = (z == 0) ? a.qpl : a.kpl;
                    ((uint32_t*)Ch)[o] = pk2(h0, h1);
                    ((uint32_t*)Cl)[o] = pk2(y0 - h0, y1 - h1);
                } else {
                    *(float2*)(a.vp + (size_t)m * 1024 + n) =
                        make_float2(v0 + bias[n], v1 + bias[n + 1]);
                }
            }
        }
    }
}

// ---------------------------------------------------------------------------
// generic GEMM: MODE 2 qk+exp fused, 3 pv, 4 oproj
// MODE 2: rZ param = emg table; Cf = Zpart; Ch/Cl = E hi/lo.
// MODE 2/3: zbase = bh offset. MODE 4: zbase = b (half), M = 4096 rows.
// ---------------------------------------------------------------------------
template <int MODE>
__global__ __launch_bounds__(256, 2) void gemm_k(
    const __nv_bfloat16* __restrict__ Ah, const __nv_bfloat16* __restrict__ Al,
    const __nv_bfloat16* __restrict__ Bh, const __nv_bfloat16* __restrict__ Bl,
    const float* __restrict__ bias, const float* __restrict__ rZ,
    float* __restrict__ Cf, __nv_bfloat16* __restrict__ Ch,
    __nv_bfloat16* __restrict__ Cl, int Kchunks, int zbase)
{
    extern __shared__ __align__(1024) char smem[];
    const uint32_t sbase = s2u(smem);
    const int tid = threadIdx.x;
    const int wid = tid >> 5, lane = tid & 31;
    const int m0 = blockIdx.y * 128, n0 = blockIdx.x * 128;
    const int z = blockIdx.z + zbase;
    const int zb = z >> 4, zh = z & 15;

    size_t a_base, b_base;
    int a_str, b_str;
    if (MODE == 2) {
        a_base = (size_t)m0 * 2048 + zb * 1024 + zh * 64; a_str = 2048;
        b_base = (size_t)n0 * 2048 + zb * 1024 + zh * 64; b_str = 2048;
    } else if (MODE == 3) {
        a_base = ((size_t)z << 20) + (size_t)m0 * 1024; a_str = 1024;
        b_base = (size_t)z * 262144 + (size_t)n0 * 1024; b_str = 1024;
    } else {
        a_base = ((size_t)zbase * 4096 + m0) * 1024; a_str = 1024;
        b_base = (size_t)n0 * 1024; b_str = 1024;
    }

    const int wm = (wid >> 2) * 64, wn = (wid & 3) * 32;

    float acc[4][4][4];
#pragma unroll
    for (int i = 0; i < 4; i++)
#pragma unroll
        for (int j = 0; j < 4; j++)
#pragma unroll
            for (int e = 0; e < 4; e++) acc[i][j][e] = 0.f;

    gemm_core(Ah, Al, Bh, Bl, a_base, a_str, b_base, b_str,
              Kchunks, sbase, tid, wm, wn, acc);

    const int tr = lane >> 2, tc2 = (lane & 3) * 2;

    if (MODE == 2) {
        // fused exp epilogue: E = exp(acc) (logits bounded, no max needed);
        // write E hi/lo; deterministic per-row/group partial-Z reduction.
        __syncthreads();   // all warps done reading stage smem
        float* emt  = (float*)smem;        // [128 s][4 g]
        float* zrow = emt + 512;           // [128 r][4 g][4 wn]
        for (int i = tid; i < 512; i += 256) {
            int s = i >> 2, g = i & 3;
            emt[i] = rZ[zb * 4096 + g * 1024 + n0 + s];   // rZ param = emg
        }
        for (int i = tid; i < 2048; i += 256) zrow[i] = 0.f;
        __syncthreads();

        const int wnid = wid & 3;
#pragma unroll
        for (int mi = 0; mi < 4; mi++) {
#pragma unroll
            for (int hr = 0; hr < 2; hr++) {
                int r = wm + 16 * mi + tr + hr * 8;
                float zp0 = 0.f, zp1 = 0.f, zp2 = 0.f, zp3 = 0.f;
#pragma unroll
                for (int nj = 0; nj < 4; nj++) {
                    int sl = wn + 8 * nj + tc2;
                    float e0 = __expf(acc[mi][nj][hr * 2 + 0]);
                    float e1 = __expf(acc[mi][nj][hr * 2 + 1]);
                    float h0 = bhi(e0), h1 = bhi(e1);
                    size_t o = (((size_t)z << 20)
                                + (size_t)(m0 + r) * 1024 + (n0 + sl)) >> 1;
                    ((uint32_t*)Ch)[o] = pk2(h0, h1);
                    ((uint32_t*)Cl)[o] = pk2(e0 - h0, e1 - h1);
                    const float* emp = &emt[sl * 4];
                    zp0 += e0 * emp[0] + e1 * emp[4];
                    zp1 += e0 * emp[1] + e1 * emp[5];
                    zp2 += e0 * emp[2] + e1 * emp[6];
                    zp3 += e0 * emp[3] + e1 * emp[7];
                }
#pragma unroll
                for (int o2 = 1; o2 < 4; o2 <<= 1) {
                    zp0 += __shfl_xor_sync(0xffffffffu, zp0, o2);
                    zp1 += __shfl_xor_sync(0xffffffffu, zp1, o2);
                    zp2 += __shfl_xor_sync(0xffffffffu, zp2, o2);
                    zp3 += __shfl_xor_sync(0xffffffffu, zp3, o2);
                }
                if ((lane & 3) == 0) {
                    zrow[(r * 4 + 0) * 4 + wnid] = zp0;
                    zrow[(r * 4 + 1) * 4 + wnid] = zp1;
                    zrow[(r * 4 + 2) * 4 + wnid] = zp2;
                    zrow[(r * 4 + 3) * 4 + wnid] = zp3;
                }
            }
        }
        __syncthreads();
        // Zpart[(z*8 + sTile)*1024 + (m0+r)]*4 + g — deterministic 4-way sum
        for (int i = tid; i < 512; i += 256) {
            int r = i >> 2, g = i & 3;
            const float* zr = &zrow[(r * 4 + g) * 4];
            float s4 = (zr[0] + zr[1]) + (zr[2] + zr[3]);
            Cf[((((size_t)z * 8 + blockIdx.x) << 10) + m0 + r) * 4 + g] = s4;
        }
        return;
    }

#pragma unroll
    for (int mi = 0; mi < 4; mi++) {
#pragma unroll
        for (int nj = 0; nj < 4; nj++) {
            int n = n0 + wn + 8 * nj + tc2;
#pragma unroll
            for (int hr = 0; hr < 2; hr++) {
                int m = m0 + wm + 16 * mi + tr + hr * 8;
                float v0 = acc[mi][nj][hr * 2 + 0];
                float v1 = acc[mi][nj][hr * 2 + 1];
                if (MODE == 3) {
                    int g = n >> 6, d = n & 63;
                    float rz = rZ[z * 4096 + g * 1024 + m];
                    float y0 = v0 * rz, y1 = v1 * rz;
                    float h0 = bhi(y0), h1 = bhi(y1);
                    size_t o = ((((size_t)zb * 4096 + g * 1024 + m) << 10)
                                + zh * 64 + d) >> 1;
                    ((uint32_t*)Ch)[o] = pk2(h0, h1);
                    ((uint32_t*)Cl)[o] = pk2(y0 - h0, y1 - h1);
                } else {
                    __stcs((float2*)(Cf + ((size_t)(2 * m + zbase) << 10) + n),
                           make_float2(v0 + bias[n], v1 + bias[n + 1]));
                }
            }
        }
    }
}

// ---------------------------------------------------------------------------
// zreduce: rZ[z][g][t] = 1 / sum_{sTile} Zpart[z][sTile][t][g]
// ---------------------------------------------------------------------------
__global__ __launch_bounds__(256) void zreduce(
    const float* __restrict__ Zpart, float* __restrict__ rZ, int zbase)
{
    int i = blockIdx.x * 256 + threadIdx.x;   // 16 * 4096
    int zl = i >> 12;
    int g = (i >> 10) & 3;
    int t = i & 1023;
    int z = zbase + zl;
    float s = 0.f;
#pragma unroll
    for (int st = 0; st < 8; st++)
        s += Zpart[((((size_t)z * 8 + st) << 10) + t) * 4 + g];
    rZ[z * 4096 + g * 1024 + t] = 1.f / s;
}

// ---------------------------------------------------------------------------
// prob_writer: prob = (Eh+El) * em * rz   (warp-per-row)
// ---------------------------------------------------------------------------
__global__ __launch_bounds__(256) void prob_writer(
    const __nv_bfloat16* __restrict__ Eh, const __nv_bfloat16* __restrict__ El,
    const float* __restrict__ emg, const float* __restrict__ rZg,
    float* __restrict__ prob_out, int bh_base)
{
    __shared__ __align__(16) float em[4][1024];

    const int tid = threadIdx.x, wid = tid >> 5, lane = tid & 31;
    const int bh = blockIdx.y + bh_base, b = bh >> 4;
    const int t = blockIdx.x * 8 + wid;

    for (int i = tid; i < 1024; i += 256)
        ((float4*)&em[0][0])[i] = ((const float4*)(emg + b * 4096))[i];
    __syncthreads();

    const size_t ebase = ((size_t)bh << 20) + (size_t)t * 1024;
    float e[32];
#pragma unroll
    for (int j = 0; j < 8; j++) {
        size_t o = (ebase + j * 128 + lane * 4) >> 2;
        uint2 hh = __ldcs(&((const uint2*)Eh)[o]);
        uint2 ll = __ldcs(&((const uint2*)El)[o]);
        float2 a0 = upk(hh.x), a1 = upk(hh.y);
        float2 b0 = upk(ll.x), b1 = upk(ll.y);
        e[4 * j + 0] = a0.x + b0.x;
        e[4 * j + 1] = a0.y + b0.y;
        e[4 * j + 2] = a1.x + b1.x;
        e[4 * j + 3] = a1.y + b1.y;
    }

    float rz[4];
#pragma unroll
    for (int g = 0; g < 4; g++) rz[g] = rZg[bh * 4096 + g * 1024 + t];

#pragma unroll
    for (int g = 0; g < 4; g++) {
        float* pout = prob_out + (((size_t)(bh * 4 + g) << 10) + t) * 1024;
        float rzg = rz[g];
#pragma unroll
        for (int j = 0; j < 8; j++) {
            float4 m = *(const float4*)&em[g][j * 128 + lane * 4];
            float4 o;
            o.x = e[4 * j + 0] * m.x * rzg;
            o.y = e[4 * j + 1] * m.y * rzg;
            o.z = e[4 * j + 2] * m.z * rzg;
            o.w = e[4 * j + 3] * m.w * rzg;
            __stcs((float4*)(pout + j * 128 + lane * 4), o);
        }
    }
}

// ---------------------------------------------------------------------------
// K3b: vgt[bh][(g*64+d)][s] = emg[b,g,s] * V[s,b,h,d]   (hi/lo bf16)
// ---------------------------------------------------------------------------
__global__ __launch_bounds__(256) void build_vg(
    const float* __restrict__ vp, const float* __restrict__ emg,
    __nv_bfloat16* __restrict__ vgh, __nv_bfloat16* __restrict__ vgl)
{
    __shared__ float vsm[64][65];
    __shared__ float em[4][64];
    const int bh = blockIdx.y, b = bh >> 4, h = bh & 15;
    const int s0 = blockIdx.x * 64;
    const int tid = threadIdx.x;

#pragma unroll
    for (int it = 0; it < 4; it++) {
        int j = it * 256 + tid;
        int r = j >> 4, c4 = (j & 15) * 4;
        float4 v = *(const float4*)(vp + (size_t)((s0 + r) * 2 + b) * 1024 + h * 64 + c4);
        vsm[r][c4] = v.x; vsm[r][c4 + 1] = v.y; vsm[r][c4 + 2] = v.z; vsm[r][c4 + 3] = v.w;
    }
    {
        int g = tid >> 6, si = tid & 63;
        em[g][si] = emg[b * 4096 + g * 1024 + s0 + si];
    }
    __syncthreads();

    const int w = tid >> 5, lane = tid & 31;
#pragma unroll 4
    for (int rr = 0; rr < 32; rr++) {
        int gd = rr * 8 + w;
        int g = gd >> 6, d = gd & 63;
        float v0 = em[g][lane * 2] * vsm[lane * 2][d];
        float v1 = em[g][lane * 2 + 1] * vsm[lane * 2 + 1][d];
        float h0 = bhi(v0), h1 = bhi(v1);
        size_t o = ((size_t)bh * 262144 + (size_t)gd * 1024 + s0 + lane * 2) >> 1;
        ((uint32_t*)vgh)[o] = pk2(h0, h1);
        ((uint32_t*)vgl)[o] = pk2(v0 - h0, v1 - h1);
    }
}

// ---------------------------------------------------------------------------
extern "C" void kernel_launch(void* const* d_in, const int* in_sizes, int n_in,
                              void* d_out, int out_size)
{
    const float* query = (const float*)d_in[0];
    const float* key   = (const float*)d_in[1];
    const unsigned char* kpm = (const unsigned char*)d_in[2];
    const float* gmask = (const float*)d_in[3];
    const float* Wq = (const float*)d_in[4];
    const float* bq = (const float*)d_in[5];
    const float* Wk = (const float*)d_in[6];
    const float* bk = (const float*)d_in[7];
    const float* Wv = (const float*)d_in[8];
    const float* bv = (const float*)d_in[9];
    const float* Wo = (const float*)d_in[10];
    const float* bo = (const float*)d_in[11];

    float* out_proj = (float*)d_out;
    float* prob_out = (float*)d_out + (size_t)4 * 1024 * 2 * 1024;

    __nv_bfloat16 *qin_h, *qin_l, *kin_h, *kin_l;
    __nv_bfloat16 *wq_h, *wq_l, *wk_h, *wk_l, *wv_h, *wv_l, *wo_h, *wo_l;
    __nv_bfloat16 *qp_h, *qp_l, *kp_h, *kp_l, *E_h, *E_l, *vgt_h, *vgt_l, *aO_h, *aO_l;
    float *vp, *zpart, *rZ, *emg;
    cudaGetSymbolAddress((void**)&qin_h, g_qin_h); cudaGetSymbolAddress((void**)&qin_l, g_qin_l);
    cudaGetSymbolAddress((void**)&kin_h, g_kin_h); cudaGetSymbolAddress((void**)&kin_l, g_kin_l);
    cudaGetSymbolAddress((void**)&wq_h, g_wq_h); cudaGetSymbolAddress((void**)&wq_l, g_wq_l);
    cudaGetSymbolAddress((void**)&wk_h, g_wk_h); cudaGetSymbolAddress((void**)&wk_l, g_wk_l);
    cudaGetSymbolAddress((void**)&wv_h, g_wv_h); cudaGetSymbolAddress((void**)&wv_l, g_wv_l);
    cudaGetSymbolAddress((void**)&wo_h, g_wo_h); cudaGetSymbolAddress((void**)&wo_l, g_wo_l);
    cudaGetSymbolAddress((void**)&qp_h, g_qp_h); cudaGetSymbolAddress((void**)&qp_l, g_qp_l);
    cudaGetSymbolAddress((void**)&kp_h, g_kp_h); cudaGetSymbolAddress((void**)&kp_l, g_kp_l);
    cudaGetSymbolAddress((void**)&vp, g_vp);
    cudaGetSymbolAddress((void**)&zpart, g_zpart);
    cudaGetSymbolAddress((void**)&E_h, g_E_h); cudaGetSymbolAddress((void**)&E_l, g_E_l);
    cudaGetSymbolAddress((void**)&rZ, g_rZ);
    cudaGetSymbolAddress((void**)&emg, g_emg);
    cudaGetSymbolAddress((void**)&vgt_h, g_vgt_h); cudaGetSymbolAddress((void**)&vgt_l, g_vgt_l);
    cudaGetSymbolAddress((void**)&aO_h, g_aO_h); cudaGetSymbolAddress((void**)&aO_l, g_aO_l);

    cudaFuncSetAttribute(gemm_qkv, cudaFuncAttributeMaxDynamicSharedMemorySize, GEMM_SMEM);
    cudaFuncSetAttribute(gemm_k<2>, cudaFuncAttributeMaxDynamicSharedMemorySize, GEMM_SMEM);
    cudaFuncSetAttribute(gemm_k<3>, cudaFuncAttributeMaxDynamicSharedMemorySize, GEMM_SMEM);
    cudaFuncSetAttribute(gemm_k<4>, cudaFuncAttributeMaxDynamicSharedMemorySize, GEMM_SMEM);

    static cudaStream_t s2 = nullptr;
    static cudaEvent_t evFork = nullptr, evVg = nullptr, evJoin = nullptr;
    if (!s2) {
        cudaStreamCreateWithFlags(&s2, cudaStreamNonBlocking);
        cudaEventCreateWithFlags(&evFork, cudaEventDisableTiming);
        cudaEventCreateWithFlags(&evVg, cudaEventDisableTiming);
        cudaEventCreateWithFlags(&evJoin, cudaEventDisableTiming);
    }

    SplitArgs sa;
    sa.src[0] = query; sa.h[0] = qin_h; sa.l[0] = qin_l;
    sa.src[1] = key;   sa.h[1] = kin_h; sa.l[1] = kin_l;
    sa.src[2] = Wq;    sa.h[2] = wq_h;  sa.l[2] = wq_l;
    sa.src[3] = Wk;    sa.h[3] = wk_h;  sa.l[3] = wk_l;
    sa.src[4] = Wv;    sa.h[4] = wv_h;  sa.l[4] = wv_l;
    sa.src[5] = Wo;    sa.h[5] = wo_h;  sa.l[5] = wo_l;
    sa.end[0] = 524288; sa.end[1] = 1048576;
    sa.end[2] = 1310720; sa.end[3] = 1572864;
    sa.end[4] = 1835008; sa.end[5] = 2097152;
    split_all_kernel<<<2097152 / 256, 256>>>(sa);
    prep_em<<<32, 256>>>(gmask, kpm, emg);

    QKVArgs qa;
    qa.qh = qin_h; qa.ql = qin_l; qa.kh = kin_h; qa.kl = kin_l;
    qa.wqh = wq_h; qa.wql = wq_l; qa.wkh = wk_h; qa.wkl = wk_l;
    qa.wvh = wv_h; qa.wvl = wv_l;
    qa.bq = bq; qa.bk = bk; qa.bv = bv;
    qa.qph = qp_h; qa.qpl = qp_l; qa.kph = kp_h; qa.kpl = kp_l;
    qa.vp = vp;
    gemm_qkv<<<dim3(8, 16, 3), 256, GEMM_SMEM>>>(qa);

    // fork
    cudaEventRecord(evFork, 0);
    cudaStreamWaitEvent(s2, evFork, 0);

    // s2: build_vg then half-1 chain (b=1, bh 16..31) + oproj(b=1)
    build_vg<<<dim3(16, 32), 256, 0, s2>>>(vp, emg, vgt_h, vgt_l);
    cudaEventRecord(evVg, s2);
    gemm_k<2><<<dim3(8, 8, 16), 256, GEMM_SMEM, s2>>>(qp_h, qp_l, kp_h, kp_l,
        nullptr, emg, zpart, E_h, E_l, 2, 16);
    zreduce<<<256, 256, 0, s2>>>(zpart, rZ, 16);
    prob_writer<<<dim3(128, 16), 256, 0, s2>>>(E_h, E_l, emg, rZ, prob_out, 16);
    gemm_k<3><<<dim3(2, 8, 16), 256, GEMM_SMEM, s2>>>(E_h, E_l, vgt_h, vgt_l,
        nullptr, rZ, nullptr, aO_h, aO_l, 32, 16);
    gemm_k<4><<<dim3(8, 32, 1), 256, GEMM_SMEM, s2>>>(aO_h, aO_l, wo_h, wo_l,
        bo, nullptr, out_proj, nullptr, nullptr, 32, 1);
    cudaEventRecord(evJoin, s2);

    // default stream: half-0 chain (b=0, bh 0..15) + oproj(b=0)
    gemm_k<2><<<dim3(8, 8, 16), 256, GEMM_SMEM>>>(qp_h, qp_l, kp_h, kp_l,
        nullptr, emg, zpart, E_h, E_l, 2, 0);
    zreduce<<<256, 256>>>(zpart, rZ, 0);
    prob_writer<<<dim3(128, 16), 256>>>(E_h, E_l, emg, rZ, prob_out, 0);
    cudaStreamWaitEvent(0, evVg, 0);
    gemm_k<3><<<dim3(2, 8, 16), 256, GEMM_SMEM>>>(E_h, E_l, vgt_h, vgt_l,
        nullptr, rZ, nullptr, aO_h, aO_l, 32, 0);
    gemm_k<4><<<dim3(8, 32, 1), 256, GEMM_SMEM>>>(aO_h, aO_l, wo_h, wo_l,
        bo, nullptr, out_proj, nullptr, nullptr, 32, 0);

    // join
    cudaStreamWaitEvent(0, evJoin, 0);
}